// round 11
// baseline (speedup 1.0000x reference)
#include <cuda_runtime.h>
#include <cuda_bf16.h>
#include <cstdint>

#define BB   4
#define SEQ  4096
#define KD   64
#define VD   128
#define NQT  32
#define NJT  32
#define SC_QCHUNK 8
#define N_SCHUNK  4
#define OUT_JCHUNK 4
#define N_OCHUNK   8

// ---------------- device scratch (allocation-free) ----------------
__device__ __align__(16) __nv_bfloat16 g_Qhi[BB * SEQ * KD];
__device__ __align__(16) __nv_bfloat16 g_Qlo[BB * SEQ * KD];
__device__ __align__(16) __nv_bfloat16 g_Khi[BB * SEQ * KD];
__device__ __align__(16) __nv_bfloat16 g_Klo[BB * SEQ * KD];
__device__ __align__(16) __nv_bfloat16 g_Vthi[BB * VD * SEQ];   // [b][v][s]
__device__ __align__(16) __nv_bfloat16 g_Vtlo[BB * VD * SEQ];
__device__ __align__(16) float  g_S[(size_t)BB * SEQ * SEQ];    // [b][q][j]
__device__ float2 g_ml[N_SCHUNK][BB][SEQ];
__device__ float  g_c[BB][SEQ];
__device__ float  g_Opart[N_OCHUNK][BB][SEQ][VD];

// ---------------- helpers ----------------
__device__ __forceinline__ uint32_t smem_u32(const void* p) {
    uint32_t a;
    asm("{ .reg .u64 t; cvta.to.shared.u64 t, %1; cvt.u32.u64 %0, t; }" : "=r"(a) : "l"(p));
    return a;
}
__device__ __forceinline__ void split_pack(float a, float b, uint32_t& hi, uint32_t& lo) {
    __nv_bfloat16 ah = __float2bfloat16(a), bh = __float2bfloat16(b);
    __nv_bfloat16 al = __float2bfloat16(a - __bfloat162float(ah));
    __nv_bfloat16 bl = __float2bfloat16(b - __bfloat162float(bh));
    hi = ((uint32_t)__bfloat16_as_ushort(bh) << 16) | __bfloat16_as_ushort(ah);
    lo = ((uint32_t)__bfloat16_as_ushort(bl) << 16) | __bfloat16_as_ushort(al);
}
__device__ __forceinline__ void mma16816(float* c, const uint32_t* a, const uint32_t* b) {
    asm volatile("mma.sync.aligned.m16n8k16.row.col.f32.bf16.bf16.f32 "
                 "{%0,%1,%2,%3}, {%4,%5,%6,%7}, {%8,%9}, {%0,%1,%2,%3};"
                 : "+f"(c[0]), "+f"(c[1]), "+f"(c[2]), "+f"(c[3])
                 : "r"(a[0]), "r"(a[1]), "r"(a[2]), "r"(a[3]), "r"(b[0]), "r"(b[1]));
}
__device__ __forceinline__ void ldmx4(uint32_t& r0, uint32_t& r1, uint32_t& r2, uint32_t& r3, uint32_t addr) {
    asm volatile("ldmatrix.sync.aligned.m8n8.x4.shared.b16 {%0,%1,%2,%3}, [%4];"
                 : "=r"(r0), "=r"(r1), "=r"(r2), "=r"(r3) : "r"(addr));
}
__device__ __forceinline__ void cp16(uint32_t dst, const void* src) {
    asm volatile("cp.async.cg.shared.global [%0], [%1], 16;" :: "r"(dst), "l"(src));
}
#define CP_COMMIT asm volatile("cp.async.commit_group;" ::: "memory")
#define CP_WAIT0  asm volatile("cp.async.wait_group 0;"  ::: "memory")

// =========================== k_proj (SIMT fp32, emits split operands) ===========================
__global__ __launch_bounds__(256, 1) void k_proj(
    const float* __restrict__ x,
    const float* __restrict__ Wq, const float* __restrict__ bq,
    const float* __restrict__ Wk, const float* __restrict__ bk,
    const float* __restrict__ Wv, const float* __restrict__ bv)
{
    extern __shared__ float sm[];
    float* xs = sm;              // [128 d][133]
    float* ws = sm + 128 * 133;
    const int tid = threadIdx.x, tx = tid & 15, ty = tid >> 4;
    const int row0 = blockIdx.x * 128;
    const int col0 = blockIdx.y * 128;   // 0: Q|K, 128: V

    #pragma unroll 4
    for (int i = tid; i < 128 * 32; i += 256) {
        int r = i >> 5, c4 = (i & 31) * 4;
        float4 v = *(const float4*)&x[(size_t)(row0 + r) * 128 + c4];
        xs[(c4 + 0) * 133 + r] = v.x; xs[(c4 + 1) * 133 + r] = v.y;
        xs[(c4 + 2) * 133 + r] = v.z; xs[(c4 + 3) * 133 + r] = v.w;
    }
    #pragma unroll 4
    for (int i = tid; i < 128 * 32; i += 256) {
        int cl = i >> 5, k4 = (i & 31) * 4;
        int col = col0 + cl;
        float4 w;
        if (col < 64)        w = *(const float4*)&Wq[col * 128 + k4];
        else if (col < 128)  w = *(const float4*)&Wk[(col - 64) * 128 + k4];
        else                 w = *(const float4*)&Wv[(col - 128) * 128 + k4];
        ws[(k4 + 0) * 133 + cl] = w.x; ws[(k4 + 1) * 133 + cl] = w.y;
        ws[(k4 + 2) * 133 + cl] = w.z; ws[(k4 + 3) * 133 + cl] = w.w;
    }
    __syncthreads();

    float acc[8][8];
    #pragma unroll
    for (int i = 0; i < 8; i++)
        #pragma unroll
        for (int j = 0; j < 8; j++) acc[i][j] = 0.f;
    for (int kk = 0; kk < 128; kk++) {
        float a[8], b[8];
        #pragma unroll
        for (int i = 0; i < 8; i++) a[i] = xs[kk * 133 + ty + 16 * i];
        #pragma unroll
        for (int j = 0; j < 8; j++) b[j] = ws[kk * 133 + tx + 16 * j];
        #pragma unroll
        for (int i = 0; i < 8; i++)
            #pragma unroll
            for (int j = 0; j < 8; j++) acc[i][j] += a[i] * b[j];
    }
    __syncthreads();
    float* st = sm;   // reuse: [128][132]
    #pragma unroll
    for (int i = 0; i < 8; i++)
        #pragma unroll
        for (int j = 0; j < 8; j++)
            st[(ty + 16 * i) * 132 + tx + 16 * j] = acc[i][j];
    __syncthreads();

    if (blockIdx.y == 0) {
        for (int i = tid; i < 128 * 64; i += 256) {
            int r = i >> 6, cp = (i & 63) * 2;
            int row = row0 + r;
            float v0 = st[r * 132 + cp], v1 = st[r * 132 + cp + 1];
            uint32_t hi, lo;
            if (cp < 64) {
                v0 = (v0 + bq[cp]) * 0.125f;
                v1 = (v1 + bq[cp + 1]) * 0.125f;
                split_pack(v0, v1, hi, lo);
                *(uint32_t*)&g_Qhi[row * KD + cp] = hi;
                *(uint32_t*)&g_Qlo[row * KD + cp] = lo;
            } else {
                int c = cp - 64;
                v0 += bk[c]; v1 += bk[c + 1];
                split_pack(v0, v1, hi, lo);
                *(uint32_t*)&g_Khi[row * KD + c] = hi;
                *(uint32_t*)&g_Klo[row * KD + c] = lo;
            }
        }
    } else {
        int bb = row0 >> 12, s0 = row0 & (SEQ - 1);
        int v = tid >> 1, h = tid & 1;
        size_t base = ((size_t)(bb * VD + v)) * SEQ + s0 + h * 64;
        float bias = bv[v];
        #pragma unroll
        for (int k2 = 0; k2 < 8; k2++) {
            uint32_t hw[4], lw[4];
            #pragma unroll
            for (int p = 0; p < 4; p++) {
                int r = h * 64 + k2 * 8 + p * 2;
                float v0 = st[r * 132 + v] + bias;
                float v1 = st[(r + 1) * 132 + v] + bias;
                split_pack(v0, v1, hw[p], lw[p]);
            }
            *(uint4*)&g_Vthi[base + k2 * 8] = make_uint4(hw[0], hw[1], hw[2], hw[3]);
            *(uint4*)&g_Vtlo[base + k2 * 8] = make_uint4(lw[0], lw[1], lw[2], lw[3]);
        }
    }
}

// =========================== k_scores (mma.sync + ldmatrix + cp.async) ===========================
// smem: Kh[128][72], Kl, Q double-buffered (Qh,Ql per buf), Sst [128][132] f32
#define SCS_K  0
#define SCS_Q(bu) (36864 + (bu) * 36864)
#define SCS_ST 110592
#define SM_SC  178176

__global__ __launch_bounds__(256, 1) void k_scores()
{
    extern __shared__ char smc[];
    const uint32_t smb = smem_u32(smc);
    float* Sst = (float*)(smc + SCS_ST);

    const int tid = threadIdx.x, lane = tid & 31, w = tid >> 5;
    const int r4 = lane >> 2, c2 = (lane & 3) * 2;
    const int qw = (w & 3) * 32, jw = (w >> 2) * 64;
    const int idx8 = lane & 7, grp = lane >> 3;
    const int arow = (grp & 1) * 8 + idx8;
    const int acolB = (grp >> 1) * 16;
    const int jt = blockIdx.x, chunk = blockIdx.y, b = blockIdx.z;
    int qt0 = jt + chunk * SC_QCHUNK;
    if (qt0 >= NQT) return;
    int qt1 = min(qt0 + SC_QCHUNK, NQT);
    const int j0 = jt * 128;

    // K tiles + first Q tile via cp.async
    for (int i = tid; i < 128 * 8; i += 256) {
        int r = i >> 3, c8 = (i & 7) * 8;
        uint32_t d = (uint32_t)(r * 72 + c8) * 2;
        cp16(smb + SCS_K + d,         &g_Khi[(size_t)(b * SEQ + j0 + r) * KD + c8]);
        cp16(smb + SCS_K + 18432 + d, &g_Klo[(size_t)(b * SEQ + j0 + r) * KD + c8]);
        cp16(smb + SCS_Q(0) + d,         &g_Qhi[(size_t)(b * SEQ + qt0 * 128 + r) * KD + c8]);
        cp16(smb + SCS_Q(0) + 18432 + d, &g_Qlo[(size_t)(b * SEQ + qt0 * 128 + r) * KD + c8]);
    }
    CP_COMMIT; CP_WAIT0;

    const int jcol = tid & 127, hh = tid >> 7;
    float mreg = -1e30f, lreg = 0.f;

    for (int qt = qt0; qt < qt1; qt++) {
        const int bu = (qt - qt0) & 1;
        __syncthreads();   // Sst free; prev-buffer MMA reads done
        if (qt + 1 < qt1) {
            for (int i = tid; i < 128 * 8; i += 256) {
                int r = i >> 3, c8 = (i & 7) * 8;
                uint32_t d = (uint32_t)(r * 72 + c8) * 2;
                cp16(smb + SCS_Q(1 - bu) + d,         &g_Qhi[(size_t)(b * SEQ + (qt + 1) * 128 + r) * KD + c8]);
                cp16(smb + SCS_Q(1 - bu) + 18432 + d, &g_Qlo[(size_t)(b * SEQ + (qt + 1) * 128 + r) * KD + c8]);
            }
            CP_COMMIT;
        }

        float acc[2][8][4];
        #pragma unroll
        for (int mt = 0; mt < 2; mt++)
            #pragma unroll
            for (int nt = 0; nt < 8; nt++)
                #pragma unroll
                for (int e = 0; e < 4; e++) acc[mt][nt][e] = 0.f;

        const uint32_t kh = smb + SCS_K, kl = kh + 18432;
        const uint32_t qh = smb + SCS_Q(bu), ql = qh + 18432;
        #pragma unroll
        for (int ks = 0; ks < 4; ks++) {
            uint32_t bh[8][2], bl[8][2];
            #pragma unroll
            for (int np = 0; np < 4; np++) {
                uint32_t off = (uint32_t)((jw + np * 16 + arow) * 72 + ks * 16) * 2 + acolB;
                uint32_t r0, r1, r2, r3;
                ldmx4(r0, r1, r2, r3, kh + off);
                bh[np*2][0] = r0; bh[np*2+1][0] = r1; bh[np*2][1] = r2; bh[np*2+1][1] = r3;
                ldmx4(r0, r1, r2, r3, kl + off);
                bl[np*2][0] = r0; bl[np*2+1][0] = r1; bl[np*2][1] = r2; bl[np*2+1][1] = r3;
            }
            #pragma unroll
            for (int mt = 0; mt < 2; mt++) {
                uint32_t off = (uint32_t)((qw + mt * 16 + arow) * 72 + ks * 16) * 2 + acolB;
                uint32_t ah[4], al[4];
                ldmx4(ah[0], ah[1], ah[2], ah[3], qh + off);
                ldmx4(al[0], al[1], al[2], al[3], ql + off);
                #pragma unroll
                for (int nt = 0; nt < 8; nt++) {
                    mma16816(acc[mt][nt], ah, bh[nt]);
                    mma16816(acc[mt][nt], ah, bl[nt]);
                    mma16816(acc[mt][nt], al, bh[nt]);
                }
            }
        }

        // mask + stage
        const bool diag = (qt == jt);
        #pragma unroll
        for (int mt = 0; mt < 2; mt++)
            #pragma unroll
            for (int nt = 0; nt < 8; nt++) {
                int jl = jw + nt * 8 + c2;
                #pragma unroll
                for (int half = 0; half < 2; half++) {
                    int ql_ = qw + mt * 16 + r4 + half * 8;
                    float v0 = acc[mt][nt][half * 2], v1 = acc[mt][nt][half * 2 + 1];
                    if (diag) {
                        if (ql_ < jl) v0 = -1e30f;
                        if (ql_ < jl + 1) v1 = -1e30f;
                    }
                    *(float2*)&Sst[ql_ * 132 + jl] = make_float2(v0, v1);
                }
            }
        CP_WAIT0;
        __syncthreads();
        // store S [b][q][j]
        size_t base = ((size_t)(b * SEQ + qt * 128)) * SEQ + j0;
        for (int i = tid; i < 128 * 32; i += 256) {
            int qq = i >> 5, f = (i & 31) * 4;
            *(float4*)&g_S[base + (size_t)qq * SEQ + f] = *(float4*)&Sst[qq * 132 + f];
        }
        // online column stats over q
        float tm = -1e30f;
        #pragma unroll 8
        for (int qq = hh * 64; qq < hh * 64 + 64; qq++) tm = fmaxf(tm, Sst[qq * 132 + jcol]);
        if (tm > mreg) { lreg *= __expf(mreg - tm); mreg = tm; }
        float ssum = 0.f;
        #pragma unroll 8
        for (int qq = hh * 64; qq < hh * 64 + 64; qq++) {
            float v = Sst[qq * 132 + jcol];
            ssum += (v > -1e29f) ? __expf(v - mreg) : 0.f;
        }
        lreg += ssum;
    }
    __syncthreads();
    float* mb2 = Sst; float* lb2 = Sst + 256;
    mb2[hh * 128 + jcol] = mreg; lb2[hh * 128 + jcol] = lreg;
    __syncthreads();
    if (tid < 128) {
        float m0 = mb2[tid], m1 = mb2[128 + tid], l0 = lb2[tid], l1 = lb2[128 + tid];
        float M = fmaxf(m0, m1);
        float L = ((m0 > -1e29f) ? l0 * __expf(m0 - M) : 0.f)
                + ((m1 > -1e29f) ? l1 * __expf(m1 - M) : 0.f);
        g_ml[chunk][b][j0 + tid] = make_float2(M, L);
    }
}

// =========================== k_combine ===========================
__global__ void k_combine()
{
    int idx = blockIdx.x * 256 + threadIdx.x;
    if (idx >= BB * SEQ) return;
    int b = idx >> 12, j = idx & (SEQ - 1);
    int jt = j >> 7;
    int nc = (NQT - 1 - jt) / SC_QCHUNK + 1;
    float M = -1e30f;
    for (int c = 0; c < nc; c++) M = fmaxf(M, g_ml[c][b][j].x);
    float L = 0.f;
    for (int c = 0; c < nc; c++) {
        float2 p = g_ml[c][b][j];
        L += (p.x > -1e29f) ? p.y * __expf(p.x - M) : 0.f;
    }
    g_c[b][j] = M + logf(L);
}

// =========================== k_out (mma.sync + ldmatrix + cp.async V) ===========================
// smem: Ph[128][136], Pl; V double-buffered (Vh,Vl per buf)
#define KOS_P 0
#define KOS_V(bu) (69632 + (bu) * 69632)
#define SM_KO 208896

__device__ __forceinline__ void ko_cpV(uint32_t smb, int b, int j0, int bu, int tid) {
    for (int i = tid; i < 128 * 16; i += 256) {
        int r = i >> 4, c8 = (i & 15) * 8;
        uint32_t d = (uint32_t)(r * 136 + c8) * 2;
        cp16(smb + KOS_V(bu) + d,         &g_Vthi[((size_t)(b * VD + r)) * SEQ + j0 + c8]);
        cp16(smb + KOS_V(bu) + 34816 + d, &g_Vtlo[((size_t)(b * VD + r)) * SEQ + j0 + c8]);
    }
    CP_COMMIT;
}
__device__ __forceinline__ void ko_fillP(char* smc, int b, int q0, int j0, int tid) {
    const int rr = tid >> 1, hf = tid & 1;
    __nv_bfloat16* Ph = (__nv_bfloat16*)(smc + KOS_P);
    __nv_bfloat16* Pl = Ph + 34816 / 2;
    const float* srow = &g_S[((size_t)(b * SEQ + q0 + rr)) * SEQ + j0 + hf * 64];
    const float* crow = &g_c[b][j0 + hf * 64];
    #pragma unroll
    for (int i = 0; i < 8; i++) {
        float4 sa = ((const float4*)srow)[i * 2];
        float4 sb = ((const float4*)srow)[i * 2 + 1];
        uint32_t hw[4], lw[4];
        split_pack(__expf(sa.x - crow[i*8+0]), __expf(sa.y - crow[i*8+1]), hw[0], lw[0]);
        split_pack(__expf(sa.z - crow[i*8+2]), __expf(sa.w - crow[i*8+3]), hw[1], lw[1]);
        split_pack(__expf(sb.x - crow[i*8+4]), __expf(sb.y - crow[i*8+5]), hw[2], lw[2]);
        split_pack(__expf(sb.z - crow[i*8+6]), __expf(sb.w - crow[i*8+7]), hw[3], lw[3]);
        *(uint4*)&Ph[rr * 136 + hf * 64 + i * 8] = make_uint4(hw[0], hw[1], hw[2], hw[3]);
        *(uint4*)&Pl[rr * 136 + hf * 64 + i * 8] = make_uint4(lw[0], lw[1], lw[2], lw[3]);
    }
}

__global__ __launch_bounds__(256, 1) void k_out()
{
    extern __shared__ char smc[];
    const uint32_t smb = smem_u32(smc);
    const int tid = threadIdx.x, lane = tid & 31, w = tid >> 5;
    const int r4 = lane >> 2, c2 = (lane & 3) * 2;
    const int qw = (w & 3) * 32, vw = (w >> 2) * 64;
    const int idx8 = lane & 7, grp = lane >> 3;
    const int arow = (grp & 1) * 8 + idx8;
    const int acolB = (grp >> 1) * 16;
    const int qt = blockIdx.x, chunk = blockIdx.y, b = blockIdx.z;
    int jt0 = chunk * OUT_JCHUNK;
    if (jt0 > qt) return;
    int jt1 = min(jt0 + OUT_JCHUNK - 1, qt);
    const int q0 = qt * 128;

    float acc[2][8][4];
    #pragma unroll
    for (int mt = 0; mt < 2; mt++)
        #pragma unroll
        for (int nt = 0; nt < 8; nt++)
            #pragma unroll
            for (int e = 0; e < 4; e++) acc[mt][nt][e] = 0.f;

    ko_cpV(smb, b, jt0 * 128, 0, tid);
    ko_fillP(smc, b, q0, jt0 * 128, tid);
    CP_WAIT0;
    __syncthreads();

    for (int jt = jt0; jt <= jt1; jt++) {
        const int bu = (jt - jt0) & 1;
        if (jt + 1 <= jt1) ko_cpV(smb, b, (jt + 1) * 128, 1 - bu, tid);

        const uint32_t ph = smb + KOS_P, pl = ph + 34816;
        const uint32_t vh = smb + KOS_V(bu), vl = vh + 34816;
        #pragma unroll
        for (int ks = 0; ks < 8; ks++) {
            uint32_t bh[8][2], bl[8][2];
            #pragma unroll
            for (int np = 0; np < 4; np++) {
                uint32_t off = (uint32_t)((vw + np * 16 + arow) * 136 + ks * 16) * 2 + acolB;
                uint32_t r0, r1, r2, r3;
                ldmx4(r0, r1, r2, r3, vh + off);
                bh[np*2][0] = r0; bh[np*2+1][0] = r1; bh[np*2][1] = r2; bh[np*2+1][1] = r3;
                ldmx4(r0, r1, r2, r3, vl + off);
                bl[np*2][0] = r0; bl[np*2+1][0] = r1; bl[np*2][1] = r2; bl[np*2+1][1] = r3;
            }
            #pragma unroll
            for (int mt = 0; mt < 2; mt++) {
                uint32_t off = (uint32_t)((qw + mt * 16 + arow) * 136 + ks * 16) * 2 + acolB;
                uint32_t ah[4], al[4];
                ldmx4(ah[0], ah[1], ah[2], ah[3], ph + off);
                ldmx4(al[0], al[1], al[2], al[3], pl + off);
                #pragma unroll
                for (int nt = 0; nt < 8; nt++) {
                    mma16816(acc[mt][nt], ah, bh[nt]);
                    mma16816(acc[mt][nt], ah, bl[nt]);
                    mma16816(acc[mt][nt], al, bh[nt]);
                }
            }
        }
        __syncthreads();                      // P reads done
        if (jt + 1 <= jt1) {
            ko_fillP(smc, b, q0, (jt + 1) * 128, tid);
            CP_WAIT0;
        }
        __syncthreads();
    }
    // deterministic partials
    #pragma unroll
    for (int mt = 0; mt < 2; mt++)
        #pragma unroll
        for (int nt = 0; nt < 8; nt++) {
            int vl_ = vw + nt * 8 + c2;
            #pragma unroll
            for (int half = 0; half < 2; half++) {
                int ql_ = qw + mt * 16 + r4 + half * 8;
                *(float2*)&g_Opart[chunk][b][q0 + ql_][vl_] =
                    make_float2(acc[mt][nt][half * 2], acc[mt][nt][half * 2 + 1]);
            }
        }
}

// =========================== k_reduce (sum partials + concat x) ===========================
__global__ void k_reduce(const float* __restrict__ x, float* __restrict__ out)
{
    int idx = blockIdx.x * 256 + threadIdx.x;
    if (idx >= BB * SEQ * 64) return;
    int c4 = (idx & 63) * 4;
    int row = idx >> 6;
    int s = row & (SEQ - 1);
    int b = row >> 12;
    float4 v;
    if (c4 < 128) {
        v = *(const float4*)&x[(size_t)row * 128 + c4];
    } else {
        int vc = c4 - 128;
        int nc = (s >> 7) / OUT_JCHUNK + 1;
        v = make_float4(0.f, 0.f, 0.f, 0.f);
        for (int c = 0; c < nc; c++) {
            float4 p = *(const float4*)&g_Opart[c][b][s][vc];
            v.x += p.x; v.y += p.y; v.z += p.z; v.w += p.w;
        }
    }
    *(float4*)&out[(size_t)row * 256 + c4] = v;
}

// =========================== launch ===========================
extern "C" void kernel_launch(void* const* d_in, const int* in_sizes, int n_in,
                              void* d_out, int out_size)
{
    const float* x  = (const float*)d_in[0];
    const float* Wq = (const float*)d_in[1];
    const float* bq = (const float*)d_in[2];
    const float* Wk = (const float*)d_in[3];
    const float* bk = (const float*)d_in[4];
    const float* Wv = (const float*)d_in[5];
    const float* bv = (const float*)d_in[6];
    float* out = (float*)d_out;

    const int SM_PROJ = (128 * 133 * 2) * 4;

    cudaFuncSetAttribute(k_proj,   cudaFuncAttributeMaxDynamicSharedMemorySize, SM_PROJ);
    cudaFuncSetAttribute(k_scores, cudaFuncAttributeMaxDynamicSharedMemorySize, SM_SC);
    cudaFuncSetAttribute(k_out,    cudaFuncAttributeMaxDynamicSharedMemorySize, SM_KO);

    k_proj<<<dim3(128, 2), 256, SM_PROJ>>>(x, Wq, bq, Wk, bk, Wv, bv);
    k_scores<<<dim3(NJT, N_SCHUNK, BB), 256, SM_SC>>>();
    k_combine<<<(BB * SEQ + 255) / 256, 256>>>();
    k_out<<<dim3(NQT, N_OCHUNK, BB), 256, SM_KO>>>();
    k_reduce<<<(BB * SEQ * 64 + 255) / 256, 256>>>(x, out);
}

// round 16
// speedup vs baseline: 1.1724x; 1.1724x over previous
#include <cuda_runtime.h>
#include <cuda_bf16.h>
#include <cstdint>

#define BB   4
#define SEQ  4096
#define KD   64
#define VD   128
#define NQT  32
#define NJT  32
#define SC_QCHUNK 8
#define N_SCHUNK  4
#define OUT_JCHUNK 4
#define N_OCHUNK   8

// ---------------- device scratch (allocation-free) ----------------
__device__ __align__(16) __nv_bfloat16 g_Qhi[BB * SEQ * KD];
__device__ __align__(16) __nv_bfloat16 g_Qlo[BB * SEQ * KD];
__device__ __align__(16) __nv_bfloat16 g_Khi[BB * SEQ * KD];
__device__ __align__(16) __nv_bfloat16 g_Klo[BB * SEQ * KD];
__device__ __align__(16) __nv_bfloat16 g_Vthi[BB * VD * SEQ];   // [b][v][s]
__device__ __align__(16) __nv_bfloat16 g_Vtlo[BB * VD * SEQ];
__device__ __align__(16) float  g_S[(size_t)BB * SEQ * SEQ];    // [b][q][j]
__device__ float2 g_ml[N_SCHUNK][BB][SEQ];
__device__ float  g_c[BB][SEQ];
__device__ float  g_Opart[N_OCHUNK][BB][SEQ][VD];

// ---------------- helpers ----------------
__device__ __forceinline__ uint32_t smem_u32(const void* p) {
    uint32_t a;
    asm("{ .reg .u64 t; cvta.to.shared.u64 t, %1; cvt.u32.u64 %0, t; }" : "=r"(a) : "l"(p));
    return a;
}
__device__ __forceinline__ void split_pack(float a, float b, uint32_t& hi, uint32_t& lo) {
    __nv_bfloat16 ah = __float2bfloat16(a), bh = __float2bfloat16(b);
    __nv_bfloat16 al = __float2bfloat16(a - __bfloat162float(ah));
    __nv_bfloat16 bl = __float2bfloat16(b - __bfloat162float(bh));
    hi = ((uint32_t)__bfloat16_as_ushort(bh) << 16) | __bfloat16_as_ushort(ah);
    lo = ((uint32_t)__bfloat16_as_ushort(bl) << 16) | __bfloat16_as_ushort(al);
}
__device__ __forceinline__ void mma16816(float* c, const uint32_t* a, const uint32_t* b) {
    asm volatile("mma.sync.aligned.m16n8k16.row.col.f32.bf16.bf16.f32 "
                 "{%0,%1,%2,%3}, {%4,%5,%6,%7}, {%8,%9}, {%0,%1,%2,%3};"
                 : "+f"(c[0]), "+f"(c[1]), "+f"(c[2]), "+f"(c[3])
                 : "r"(a[0]), "r"(a[1]), "r"(a[2]), "r"(a[3]), "r"(b[0]), "r"(b[1]));
}
__device__ __forceinline__ void ldmx4(uint32_t& r0, uint32_t& r1, uint32_t& r2, uint32_t& r3, uint32_t addr) {
    asm volatile("ldmatrix.sync.aligned.m8n8.x4.shared.b16 {%0,%1,%2,%3}, [%4];"
                 : "=r"(r0), "=r"(r1), "=r"(r2), "=r"(r3) : "r"(addr));
}
__device__ __forceinline__ void cp16(uint32_t dst, const void* src) {
    asm volatile("cp.async.cg.shared.global [%0], [%1], 16;" :: "r"(dst), "l"(src));
}
#define CP_COMMIT asm volatile("cp.async.commit_group;" ::: "memory")
#define CP_WAIT0  asm volatile("cp.async.wait_group 0;"  ::: "memory")

// =========================== k_proj (SIMT fp32, emits split operands) ===========================
__global__ __launch_bounds__(256, 1) void k_proj(
    const float* __restrict__ x,
    const float* __restrict__ Wq, const float* __restrict__ bq,
    const float* __restrict__ Wk, const float* __restrict__ bk,
    const float* __restrict__ Wv, const float* __restrict__ bv)
{
    extern __shared__ float sm[];
    float* xs = sm;              // [128 d][133]
    float* ws = sm + 128 * 133;
    const int tid = threadIdx.x, tx = tid & 15, ty = tid >> 4;
    const int row0 = blockIdx.x * 128;
    const int col0 = blockIdx.y * 128;   // 0: Q|K, 128: V

    #pragma unroll 4
    for (int i = tid; i < 128 * 32; i += 256) {
        int r = i >> 5, c4 = (i & 31) * 4;
        float4 v = *(const float4*)&x[(size_t)(row0 + r) * 128 + c4];
        xs[(c4 + 0) * 133 + r] = v.x; xs[(c4 + 1) * 133 + r] = v.y;
        xs[(c4 + 2) * 133 + r] = v.z; xs[(c4 + 3) * 133 + r] = v.w;
    }
    #pragma unroll 4
    for (int i = tid; i < 128 * 32; i += 256) {
        int cl = i >> 5, k4 = (i & 31) * 4;
        int col = col0 + cl;
        float4 w;
        if (col < 64)        w = *(const float4*)&Wq[col * 128 + k4];
        else if (col < 128)  w = *(const float4*)&Wk[(col - 64) * 128 + k4];
        else                 w = *(const float4*)&Wv[(col - 128) * 128 + k4];
        ws[(k4 + 0) * 133 + cl] = w.x; ws[(k4 + 1) * 133 + cl] = w.y;
        ws[(k4 + 2) * 133 + cl] = w.z; ws[(k4 + 3) * 133 + cl] = w.w;
    }
    __syncthreads();

    float acc[8][8];
    #pragma unroll
    for (int i = 0; i < 8; i++)
        #pragma unroll
        for (int j = 0; j < 8; j++) acc[i][j] = 0.f;
    for (int kk = 0; kk < 128; kk++) {
        float a[8], b[8];
        #pragma unroll
        for (int i = 0; i < 8; i++) a[i] = xs[kk * 133 + ty + 16 * i];
        #pragma unroll
        for (int j = 0; j < 8; j++) b[j] = ws[kk * 133 + tx + 16 * j];
        #pragma unroll
        for (int i = 0; i < 8; i++)
            #pragma unroll
            for (int j = 0; j < 8; j++) acc[i][j] += a[i] * b[j];
    }
    __syncthreads();
    float* st = sm;   // reuse: [128][132]
    #pragma unroll
    for (int i = 0; i < 8; i++)
        #pragma unroll
        for (int j = 0; j < 8; j++)
            st[(ty + 16 * i) * 132 + tx + 16 * j] = acc[i][j];
    __syncthreads();

    if (blockIdx.y == 0) {
        for (int i = tid; i < 128 * 64; i += 256) {
            int r = i >> 6, cp = (i & 63) * 2;
            int row = row0 + r;
            float v0 = st[r * 132 + cp], v1 = st[r * 132 + cp + 1];
            uint32_t hi, lo;
            if (cp < 64) {
                v0 = (v0 + bq[cp]) * 0.125f;
                v1 = (v1 + bq[cp + 1]) * 0.125f;
                split_pack(v0, v1, hi, lo);
                *(uint32_t*)&g_Qhi[row * KD + cp] = hi;
                *(uint32_t*)&g_Qlo[row * KD + cp] = lo;
            } else {
                int c = cp - 64;
                v0 += bk[c]; v1 += bk[c + 1];
                split_pack(v0, v1, hi, lo);
                *(uint32_t*)&g_Khi[row * KD + c] = hi;
                *(uint32_t*)&g_Klo[row * KD + c] = lo;
            }
        }
    } else {
        int bb = row0 >> 12, s0 = row0 & (SEQ - 1);
        int v = tid >> 1, h = tid & 1;
        size_t base = ((size_t)(bb * VD + v)) * SEQ + s0 + h * 64;
        float bias = bv[v];
        #pragma unroll
        for (int k2 = 0; k2 < 8; k2++) {
            uint32_t hw[4], lw[4];
            #pragma unroll
            for (int p = 0; p < 4; p++) {
                int r = h * 64 + k2 * 8 + p * 2;
                float v0 = st[r * 132 + v] + bias;
                float v1 = st[(r + 1) * 132 + v] + bias;
                split_pack(v0, v1, hw[p], lw[p]);
            }
            *(uint4*)&g_Vthi[base + k2 * 8] = make_uint4(hw[0], hw[1], hw[2], hw[3]);
            *(uint4*)&g_Vtlo[base + k2 * 8] = make_uint4(lw[0], lw[1], lw[2], lw[3]);
        }
    }
}

// =========================== k_scores (unchanged from R11) ===========================
#define SCS_K  0
#define SCS_Q(bu) (36864 + (bu) * 36864)
#define SCS_ST 110592
#define SM_SC  178176

__global__ __launch_bounds__(256, 1) void k_scores()
{
    extern __shared__ char smc[];
    const uint32_t smb = smem_u32(smc);
    float* Sst = (float*)(smc + SCS_ST);

    const int tid = threadIdx.x, lane = tid & 31, w = tid >> 5;
    const int r4 = lane >> 2, c2 = (lane & 3) * 2;
    const int qw = (w & 3) * 32, jw = (w >> 2) * 64;
    const int idx8 = lane & 7, grp = lane >> 3;
    const int arow = (grp & 1) * 8 + idx8;
    const int acolB = (grp >> 1) * 16;
    const int jt = blockIdx.x, chunk = blockIdx.y, b = blockIdx.z;
    int qt0 = jt + chunk * SC_QCHUNK;
    if (qt0 >= NQT) return;
    int qt1 = min(qt0 + SC_QCHUNK, NQT);
    const int j0 = jt * 128;

    for (int i = tid; i < 128 * 8; i += 256) {
        int r = i >> 3, c8 = (i & 7) * 8;
        uint32_t d = (uint32_t)(r * 72 + c8) * 2;
        cp16(smb + SCS_K + d,         &g_Khi[(size_t)(b * SEQ + j0 + r) * KD + c8]);
        cp16(smb + SCS_K + 18432 + d, &g_Klo[(size_t)(b * SEQ + j0 + r) * KD + c8]);
        cp16(smb + SCS_Q(0) + d,         &g_Qhi[(size_t)(b * SEQ + qt0 * 128 + r) * KD + c8]);
        cp16(smb + SCS_Q(0) + 18432 + d, &g_Qlo[(size_t)(b * SEQ + qt0 * 128 + r) * KD + c8]);
    }
    CP_COMMIT; CP_WAIT0;

    const int jcol = tid & 127, hh = tid >> 7;
    float mreg = -1e30f, lreg = 0.f;

    for (int qt = qt0; qt < qt1; qt++) {
        const int bu = (qt - qt0) & 1;
        __syncthreads();
        if (qt + 1 < qt1) {
            for (int i = tid; i < 128 * 8; i += 256) {
                int r = i >> 3, c8 = (i & 7) * 8;
                uint32_t d = (uint32_t)(r * 72 + c8) * 2;
                cp16(smb + SCS_Q(1 - bu) + d,         &g_Qhi[(size_t)(b * SEQ + (qt + 1) * 128 + r) * KD + c8]);
                cp16(smb + SCS_Q(1 - bu) + 18432 + d, &g_Qlo[(size_t)(b * SEQ + (qt + 1) * 128 + r) * KD + c8]);
            }
            CP_COMMIT;
        }

        float acc[2][8][4];
        #pragma unroll
        for (int mt = 0; mt < 2; mt++)
            #pragma unroll
            for (int nt = 0; nt < 8; nt++)
                #pragma unroll
                for (int e = 0; e < 4; e++) acc[mt][nt][e] = 0.f;

        const uint32_t kh = smb + SCS_K, kl = kh + 18432;
        const uint32_t qh = smb + SCS_Q(bu), ql = qh + 18432;
        #pragma unroll
        for (int ks = 0; ks < 4; ks++) {
            uint32_t bh[8][2], bl[8][2];
            #pragma unroll
            for (int np = 0; np < 4; np++) {
                uint32_t off = (uint32_t)((jw + np * 16 + arow) * 72 + ks * 16) * 2 + acolB;
                uint32_t r0, r1, r2, r3;
                ldmx4(r0, r1, r2, r3, kh + off);
                bh[np*2][0] = r0; bh[np*2+1][0] = r1; bh[np*2][1] = r2; bh[np*2+1][1] = r3;
                ldmx4(r0, r1, r2, r3, kl + off);
                bl[np*2][0] = r0; bl[np*2+1][0] = r1; bl[np*2][1] = r2; bl[np*2+1][1] = r3;
            }
            #pragma unroll
            for (int mt = 0; mt < 2; mt++) {
                uint32_t off = (uint32_t)((qw + mt * 16 + arow) * 72 + ks * 16) * 2 + acolB;
                uint32_t ah[4], al[4];
                ldmx4(ah[0], ah[1], ah[2], ah[3], qh + off);
                ldmx4(al[0], al[1], al[2], al[3], ql + off);
                #pragma unroll
                for (int nt = 0; nt < 8; nt++) {
                    mma16816(acc[mt][nt], ah, bh[nt]);
                    mma16816(acc[mt][nt], ah, bl[nt]);
                    mma16816(acc[mt][nt], al, bh[nt]);
                }
            }
        }

        const bool diag = (qt == jt);
        #pragma unroll
        for (int mt = 0; mt < 2; mt++)
            #pragma unroll
            for (int nt = 0; nt < 8; nt++) {
                int jl = jw + nt * 8 + c2;
                #pragma unroll
                for (int half = 0; half < 2; half++) {
                    int ql_ = qw + mt * 16 + r4 + half * 8;
                    float v0 = acc[mt][nt][half * 2], v1 = acc[mt][nt][half * 2 + 1];
                    if (diag) {
                        if (ql_ < jl) v0 = -1e30f;
                        if (ql_ < jl + 1) v1 = -1e30f;
                    }
                    *(float2*)&Sst[ql_ * 132 + jl] = make_float2(v0, v1);
                }
            }
        CP_WAIT0;
        __syncthreads();
        size_t base = ((size_t)(b * SEQ + qt * 128)) * SEQ + j0;
        for (int i = tid; i < 128 * 32; i += 256) {
            int qq = i >> 5, f = (i & 31) * 4;
            *(float4*)&g_S[base + (size_t)qq * SEQ + f] = *(float4*)&Sst[qq * 132 + f];
        }
        float tm = -1e30f;
        #pragma unroll 8
        for (int qq = hh * 64; qq < hh * 64 + 64; qq++) tm = fmaxf(tm, Sst[qq * 132 + jcol]);
        if (tm > mreg) { lreg *= __expf(mreg - tm); mreg = tm; }
        float ssum = 0.f;
        #pragma unroll 8
        for (int qq = hh * 64; qq < hh * 64 + 64; qq++) {
            float v = Sst[qq * 132 + jcol];
            ssum += (v > -1e29f) ? __expf(v - mreg) : 0.f;
        }
        lreg += ssum;
    }
    __syncthreads();
    float* mb2 = Sst; float* lb2 = Sst + 256;
    mb2[hh * 128 + jcol] = mreg; lb2[hh * 128 + jcol] = lreg;
    __syncthreads();
    if (tid < 128) {
        float m0 = mb2[tid], m1 = mb2[128 + tid], l0 = lb2[tid], l1 = lb2[128 + tid];
        float M = fmaxf(m0, m1);
        float L = ((m0 > -1e29f) ? l0 * __expf(m0 - M) : 0.f)
                + ((m1 > -1e29f) ? l1 * __expf(m1 - M) : 0.f);
        g_ml[chunk][b][j0 + tid] = make_float2(M, L);
    }
}

// =========================== k_combine ===========================
__global__ void k_combine()
{
    int idx = blockIdx.x * 256 + threadIdx.x;
    if (idx >= BB * SEQ) return;
    int b = idx >> 12, j = idx & (SEQ - 1);
    int jt = j >> 7;
    int nc = (NQT - 1 - jt) / SC_QCHUNK + 1;
    float M = -1e30f;
    for (int c = 0; c < nc; c++) M = fmaxf(M, g_ml[c][b][j].x);
    float L = 0.f;
    for (int c = 0; c < nc; c++) {
        float2 p = g_ml[c][b][j];
        L += (p.x > -1e29f) ? p.y * __expf(p.x - M) : 0.f;
    }
    g_c[b][j] = M + logf(L);
}

// =========================== k_out (64-wide j chunks, 2 CTAs/SM) ===========================
// smem: Ph[128][72]+Pl (36864); V db: per buf Vh[128][72]+Vl (36864)
#define KOS_P 0
#define KOS_V(bu) (36864 + (bu) * 36864)
#define SM_KO 110592

__device__ __forceinline__ void ko_cpV(uint32_t smb, int b, int jc, int bu, int tid) {
    for (int i = tid; i < 128 * 8; i += 256) {
        int r = i >> 3, c8 = (i & 7) * 8;
        uint32_t d = (uint32_t)(r * 72 + c8) * 2;
        cp16(smb + KOS_V(bu) + d,         &g_Vthi[((size_t)(b * VD + r)) * SEQ + jc * 64 + c8]);
        cp16(smb + KOS_V(bu) + 18432 + d, &g_Vtlo[((size_t)(b * VD + r)) * SEQ + jc * 64 + c8]);
    }
    CP_COMMIT;
}
__device__ __forceinline__ void ko_fillP(char* smc, int b, int q0, int jc, int tid) {
    const int rr = tid >> 1, hf = tid & 1;
    __nv_bfloat16* Ph = (__nv_bfloat16*)(smc + KOS_P);
    __nv_bfloat16* Pl = (__nv_bfloat16*)(smc + KOS_P + 18432);
    const float* srow = &g_S[((size_t)(b * SEQ + q0 + rr)) * SEQ + jc * 64 + hf * 32];
    const float* crow = &g_c[b][jc * 64 + hf * 32];
    #pragma unroll
    for (int i = 0; i < 4; i++) {
        float4 sa = ((const float4*)srow)[i * 2];
        float4 sb = ((const float4*)srow)[i * 2 + 1];
        uint32_t hw[4], lw[4];
        split_pack(__expf(sa.x - crow[i*8+0]), __expf(sa.y - crow[i*8+1]), hw[0], lw[0]);
        split_pack(__expf(sa.z - crow[i*8+2]), __expf(sa.w - crow[i*8+3]), hw[1], lw[1]);
        split_pack(__expf(sb.x - crow[i*8+4]), __expf(sb.y - crow[i*8+5]), hw[2], lw[2]);
        split_pack(__expf(sb.z - crow[i*8+6]), __expf(sb.w - crow[i*8+7]), hw[3], lw[3]);
        *(uint4*)&Ph[rr * 72 + hf * 32 + i * 8] = make_uint4(hw[0], hw[1], hw[2], hw[3]);
        *(uint4*)&Pl[rr * 72 + hf * 32 + i * 8] = make_uint4(lw[0], lw[1], lw[2], lw[3]);
    }
}

__global__ __launch_bounds__(256, 2) void k_out()
{
    extern __shared__ char smc[];
    const uint32_t smb = smem_u32(smc);
    const int tid = threadIdx.x, lane = tid & 31, w = tid >> 5;
    const int r4 = lane >> 2, c2 = (lane & 3) * 2;
    const int qw = (w & 3) * 32, vw = (w >> 2) * 64;
    const int idx8 = lane & 7, grp = lane >> 3;
    const int arow = (grp & 1) * 8 + idx8;
    const int acolB = (grp >> 1) * 16;
    const int qt = blockIdx.x, chunk = blockIdx.y, b = blockIdx.z;
    int jt0 = chunk * OUT_JCHUNK;
    if (jt0 > qt) return;
    int jt1 = min(jt0 + OUT_JCHUNK - 1, qt);
    const int q0 = qt * 128;
    const int jc0 = jt0 * 2, nch = (jt1 - jt0 + 1) * 2;

    float acc[2][8][4];
    #pragma unroll
    for (int mt = 0; mt < 2; mt++)
        #pragma unroll
        for (int nt = 0; nt < 8; nt++)
            #pragma unroll
            for (int e = 0; e < 4; e++) acc[mt][nt][e] = 0.f;

    ko_cpV(smb, b, jc0, 0, tid);
    ko_fillP(smc, b, q0, jc0, tid);
    CP_WAIT0;
    __syncthreads();

    for (int c = 0; c < nch; c++) {
        const int bu = c & 1;
        if (c + 1 < nch) ko_cpV(smb, b, jc0 + c + 1, 1 - bu, tid);

        const uint32_t ph = smb + KOS_P, pl = ph + 18432;
        const uint32_t vh = smb + KOS_V(bu), vl = vh + 18432;
        #pragma unroll
        for (int ks = 0; ks < 4; ks++) {
            uint32_t ah[2][4], al[2][4];
            #pragma unroll
            for (int mt = 0; mt < 2; mt++) {
                uint32_t offA = (uint32_t)((qw + mt * 16 + arow) * 72 + ks * 16) * 2 + acolB;
                ldmx4(ah[mt][0], ah[mt][1], ah[mt][2], ah[mt][3], ph + offA);
                ldmx4(al[mt][0], al[mt][1], al[mt][2], al[mt][3], pl + offA);
            }
            #pragma unroll
            for (int np = 0; np < 4; np++) {
                uint32_t offB = (uint32_t)((vw + np * 16 + arow) * 72 + ks * 16) * 2 + acolB;
                uint32_t x0, x1, x2, x3, y0, y1, y2, y3;
                ldmx4(x0, x1, x2, x3, vh + offB);
                ldmx4(y0, y1, y2, y3, vl + offB);
                uint32_t bhA[2] = {x0, x2}, bhB[2] = {x1, x3};
                uint32_t blA[2] = {y0, y2}, blB[2] = {y1, y3};
                #pragma unroll
                for (int mt = 0; mt < 2; mt++) {
                    mma16816(acc[mt][2*np],     ah[mt], bhA);
                    mma16816(acc[mt][2*np],     ah[mt], blA);
                    mma16816(acc[mt][2*np],     al[mt], bhA);
                    mma16816(acc[mt][2*np + 1], ah[mt], bhB);
                    mma16816(acc[mt][2*np + 1], ah[mt], blB);
                    mma16816(acc[mt][2*np + 1], al[mt], bhB);
                }
            }
        }
        __syncthreads();                      // P reads done
        if (c + 1 < nch) {
            ko_fillP(smc, b, q0, jc0 + c + 1, tid);
            CP_WAIT0;
        }
        __syncthreads();
    }
    // deterministic partials
    #pragma unroll
    for (int mt = 0; mt < 2; mt++)
        #pragma unroll
        for (int nt = 0; nt < 8; nt++) {
            int vl_ = vw + nt * 8 + c2;
            #pragma unroll
            for (int half = 0; half < 2; half++) {
                int ql_ = qw + mt * 16 + r4 + half * 8;
                *(float2*)&g_Opart[chunk][b][q0 + ql_][vl_] =
                    make_float2(acc[mt][nt][half * 2], acc[mt][nt][half * 2 + 1]);
            }
        }
}

// =========================== k_reduce (sum partials + concat x) ===========================
__global__ void k_reduce(const float* __restrict__ x, float* __restrict__ out)
{
    int idx = blockIdx.x * 256 + threadIdx.x;
    if (idx >= BB * SEQ * 64) return;
    int c4 = (idx & 63) * 4;
    int row = idx >> 6;
    int s = row & (SEQ - 1);
    int b = row >> 12;
    float4 v;
    if (c4 < 128) {
        v = *(const float4*)&x[(size_t)row * 128 + c4];
    } else {
        int vc = c4 - 128;
        int nc = (s >> 7) / OUT_JCHUNK + 1;
        v = make_float4(0.f, 0.f, 0.f, 0.f);
        for (int c = 0; c < nc; c++) {
            float4 p = *(const float4*)&g_Opart[c][b][s][vc];
            v.x += p.x; v.y += p.y; v.z += p.z; v.w += p.w;
        }
    }
    *(float4*)&out[(size_t)row * 256 + c4] = v;
}

// =========================== launch ===========================
extern "C" void kernel_launch(void* const* d_in, const int* in_sizes, int n_in,
                              void* d_out, int out_size)
{
    const float* x  = (const float*)d_in[0];
    const float* Wq = (const float*)d_in[1];
    const float* bq = (const float*)d_in[2];
    const float* Wk = (const float*)d_in[3];
    const float* bk = (const float*)d_in[4];
    const float* Wv = (const float*)d_in[5];
    const float* bv = (const float*)d_in[6];
    float* out = (float*)d_out;

    const int SM_PROJ = (128 * 133 * 2) * 4;

    cudaFuncSetAttribute(k_proj,   cudaFuncAttributeMaxDynamicSharedMemorySize, SM_PROJ);
    cudaFuncSetAttribute(k_scores, cudaFuncAttributeMaxDynamicSharedMemorySize, SM_SC);
    cudaFuncSetAttribute(k_out,    cudaFuncAttributeMaxDynamicSharedMemorySize, SM_KO);

    k_proj<<<dim3(128, 2), 256, SM_PROJ>>>(x, Wq, bq, Wk, bk, Wv, bv);
    k_scores<<<dim3(NJT, N_SCHUNK, BB), 256, SM_SC>>>();
    k_combine<<<(BB * SEQ + 255) / 256, 256>>>();
    k_out<<<dim3(NQT, N_OCHUNK, BB), 256, SM_KO>>>();
    k_reduce<<<(BB * SEQ * 64 + 255) / 256, 256>>>(x, out);
}

// round 17
// speedup vs baseline: 1.2300x; 1.0491x over previous
#include <cuda_runtime.h>
#include <cuda_bf16.h>
#include <cstdint>

#define BB   4
#define SEQ  4096
#define KD   64
#define VD   128
#define NQT  32
#define NJT  32
#define SC_QCHUNK 8
#define N_SCHUNK  4
#define OUT_JCHUNK 4
#define N_OCHUNK   8

// ---------------- device scratch (allocation-free) ----------------
__device__ __align__(16) __nv_bfloat16 g_Qhi[BB * SEQ * KD];
__device__ __align__(16) __nv_bfloat16 g_Qlo[BB * SEQ * KD];
__device__ __align__(16) __nv_bfloat16 g_Khi[BB * SEQ * KD];
__device__ __align__(16) __nv_bfloat16 g_Klo[BB * SEQ * KD];
__device__ __align__(16) __nv_bfloat16 g_Vthi[BB * VD * SEQ];   // [b][v][s]
__device__ __align__(16) __nv_bfloat16 g_Vtlo[BB * VD * SEQ];
__device__ __align__(16) float  g_S[(size_t)BB * SEQ * SEQ];    // [b][q][j]
__device__ float2 g_ml[N_SCHUNK][BB][SEQ];
__device__ float  g_c[BB][SEQ];
__device__ float  g_Opart[N_OCHUNK][BB][SEQ][VD];

// ---------------- helpers ----------------
__device__ __forceinline__ uint32_t smem_u32(const void* p) {
    uint32_t a;
    asm("{ .reg .u64 t; cvta.to.shared.u64 t, %1; cvt.u32.u64 %0, t; }" : "=r"(a) : "l"(p));
    return a;
}
__device__ __forceinline__ void split_pack(float a, float b, uint32_t& hi, uint32_t& lo) {
    __nv_bfloat16 ah = __float2bfloat16(a), bh = __float2bfloat16(b);
    __nv_bfloat16 al = __float2bfloat16(a - __bfloat162float(ah));
    __nv_bfloat16 bl = __float2bfloat16(b - __bfloat162float(bh));
    hi = ((uint32_t)__bfloat16_as_ushort(bh) << 16) | __bfloat16_as_ushort(ah);
    lo = ((uint32_t)__bfloat16_as_ushort(bl) << 16) | __bfloat16_as_ushort(al);
}
__device__ __forceinline__ void mma16816(float* c, const uint32_t* a, const uint32_t* b) {
    asm volatile("mma.sync.aligned.m16n8k16.row.col.f32.bf16.bf16.f32 "
                 "{%0,%1,%2,%3}, {%4,%5,%6,%7}, {%8,%9}, {%0,%1,%2,%3};"
                 : "+f"(c[0]), "+f"(c[1]), "+f"(c[2]), "+f"(c[3])
                 : "r"(a[0]), "r"(a[1]), "r"(a[2]), "r"(a[3]), "r"(b[0]), "r"(b[1]));
}
__device__ __forceinline__ void ldmx4(uint32_t& r0, uint32_t& r1, uint32_t& r2, uint32_t& r3, uint32_t addr) {
    asm volatile("ldmatrix.sync.aligned.m8n8.x4.shared.b16 {%0,%1,%2,%3}, [%4];"
                 : "=r"(r0), "=r"(r1), "=r"(r2), "=r"(r3) : "r"(addr));
}
__device__ __forceinline__ void cp16(uint32_t dst, const void* src) {
    asm volatile("cp.async.cg.shared.global [%0], [%1], 16;" :: "r"(dst), "l"(src));
}
#define CP_COMMIT asm volatile("cp.async.commit_group;" ::: "memory")
#define CP_WAIT0  asm volatile("cp.async.wait_group 0;"  ::: "memory")

// =========================== k_proj (SIMT fp32, emits split operands) ===========================
__global__ __launch_bounds__(256, 1) void k_proj(
    const float* __restrict__ x,
    const float* __restrict__ Wq, const float* __restrict__ bq,
    const float* __restrict__ Wk, const float* __restrict__ bk,
    const float* __restrict__ Wv, const float* __restrict__ bv)
{
    extern __shared__ float sm[];
    float* xs = sm;              // [128 d][133]
    float* ws = sm + 128 * 133;
    const int tid = threadIdx.x, tx = tid & 15, ty = tid >> 4;
    const int row0 = blockIdx.x * 128;
    const int col0 = blockIdx.y * 128;   // 0: Q|K, 128: V

    #pragma unroll 4
    for (int i = tid; i < 128 * 32; i += 256) {
        int r = i >> 5, c4 = (i & 31) * 4;
        float4 v = *(const float4*)&x[(size_t)(row0 + r) * 128 + c4];
        xs[(c4 + 0) * 133 + r] = v.x; xs[(c4 + 1) * 133 + r] = v.y;
        xs[(c4 + 2) * 133 + r] = v.z; xs[(c4 + 3) * 133 + r] = v.w;
    }
    #pragma unroll 4
    for (int i = tid; i < 128 * 32; i += 256) {
        int cl = i >> 5, k4 = (i & 31) * 4;
        int col = col0 + cl;
        float4 w;
        if (col < 64)        w = *(const float4*)&Wq[col * 128 + k4];
        else if (col < 128)  w = *(const float4*)&Wk[(col - 64) * 128 + k4];
        else                 w = *(const float4*)&Wv[(col - 128) * 128 + k4];
        ws[(k4 + 0) * 133 + cl] = w.x; ws[(k4 + 1) * 133 + cl] = w.y;
        ws[(k4 + 2) * 133 + cl] = w.z; ws[(k4 + 3) * 133 + cl] = w.w;
    }
    __syncthreads();

    float acc[8][8];
    #pragma unroll
    for (int i = 0; i < 8; i++)
        #pragma unroll
        for (int j = 0; j < 8; j++) acc[i][j] = 0.f;
    for (int kk = 0; kk < 128; kk++) {
        float a[8], b[8];
        #pragma unroll
        for (int i = 0; i < 8; i++) a[i] = xs[kk * 133 + ty + 16 * i];
        #pragma unroll
        for (int j = 0; j < 8; j++) b[j] = ws[kk * 133 + tx + 16 * j];
        #pragma unroll
        for (int i = 0; i < 8; i++)
            #pragma unroll
            for (int j = 0; j < 8; j++) acc[i][j] += a[i] * b[j];
    }
    __syncthreads();
    float* st = sm;   // reuse: [128][132]
    #pragma unroll
    for (int i = 0; i < 8; i++)
        #pragma unroll
        for (int j = 0; j < 8; j++)
            st[(ty + 16 * i) * 132 + tx + 16 * j] = acc[i][j];
    __syncthreads();

    if (blockIdx.y == 0) {
        for (int i = tid; i < 128 * 64; i += 256) {
            int r = i >> 6, cp = (i & 63) * 2;
            int row = row0 + r;
            float v0 = st[r * 132 + cp], v1 = st[r * 132 + cp + 1];
            uint32_t hi, lo;
            if (cp < 64) {
                v0 = (v0 + bq[cp]) * 0.125f;
                v1 = (v1 + bq[cp + 1]) * 0.125f;
                split_pack(v0, v1, hi, lo);
                *(uint32_t*)&g_Qhi[row * KD + cp] = hi;
                *(uint32_t*)&g_Qlo[row * KD + cp] = lo;
            } else {
                int c = cp - 64;
                v0 += bk[c]; v1 += bk[c + 1];
                split_pack(v0, v1, hi, lo);
                *(uint32_t*)&g_Khi[row * KD + c] = hi;
                *(uint32_t*)&g_Klo[row * KD + c] = lo;
            }
        }
    } else {
        int bb = row0 >> 12, s0 = row0 & (SEQ - 1);
        int v = tid >> 1, h = tid & 1;
        size_t base = ((size_t)(bb * VD + v)) * SEQ + s0 + h * 64;
        float bias = bv[v];
        #pragma unroll
        for (int k2 = 0; k2 < 8; k2++) {
            uint32_t hw[4], lw[4];
            #pragma unroll
            for (int p = 0; p < 4; p++) {
                int r = h * 64 + k2 * 8 + p * 2;
                float v0 = st[r * 132 + v] + bias;
                float v1 = st[(r + 1) * 132 + v] + bias;
                split_pack(v0, v1, hw[p], lw[p]);
            }
            *(uint4*)&g_Vthi[base + k2 * 8] = make_uint4(hw[0], hw[1], hw[2], hw[3]);
            *(uint4*)&g_Vtlo[base + k2 * 8] = make_uint4(lw[0], lw[1], lw[2], lw[3]);
        }
    }
}

// =========================== k_scores (2 CTAs/SM, register stats, direct S store) ===========================
// smem: Kh+Kl (36864), Q db 2x36864. Stats buffer (4KB) reuses Q(0) after the loop.
#define SCS_K  0
#define SCS_Q(bu) (36864 + (bu) * 36864)
#define SM_SC  110592

__global__ __launch_bounds__(256, 2) void k_scores()
{
    extern __shared__ char smc[];
    const uint32_t smb = smem_u32(smc);

    const int tid = threadIdx.x, lane = tid & 31, w = tid >> 5;
    const int r4 = lane >> 2, cg = lane & 3, c2 = cg * 2;
    const int qw = (w & 3) * 32, jw = (w >> 2) * 64;
    const int idx8 = lane & 7, grp = lane >> 3;
    const int arow = (grp & 1) * 8 + idx8;
    const int acolB = (grp >> 1) * 16;
    const int jt = blockIdx.x, chunk = blockIdx.y, b = blockIdx.z;
    int qt0 = jt + chunk * SC_QCHUNK;
    if (qt0 >= NQT) return;
    int qt1 = min(qt0 + SC_QCHUNK, NQT);
    const int j0 = jt * 128;

    for (int i = tid; i < 128 * 8; i += 256) {
        int r = i >> 3, c8 = (i & 7) * 8;
        uint32_t d = (uint32_t)(r * 72 + c8) * 2;
        cp16(smb + SCS_K + d,         &g_Khi[(size_t)(b * SEQ + j0 + r) * KD + c8]);
        cp16(smb + SCS_K + 18432 + d, &g_Klo[(size_t)(b * SEQ + j0 + r) * KD + c8]);
        cp16(smb + SCS_Q(0) + d,         &g_Qhi[(size_t)(b * SEQ + qt0 * 128 + r) * KD + c8]);
        cp16(smb + SCS_Q(0) + 18432 + d, &g_Qlo[(size_t)(b * SEQ + qt0 * 128 + r) * KD + c8]);
    }
    CP_COMMIT; CP_WAIT0;

    float mrun[2] = {-1e30f, -1e30f}, lrun[2] = {0.f, 0.f};

    for (int qt = qt0; qt < qt1; qt++) {
        const int bu = (qt - qt0) & 1;
        __syncthreads();   // cp.async data visible; prev-buffer MMA reads done
        if (qt + 1 < qt1) {
            for (int i = tid; i < 128 * 8; i += 256) {
                int r = i >> 3, c8 = (i & 7) * 8;
                uint32_t d = (uint32_t)(r * 72 + c8) * 2;
                cp16(smb + SCS_Q(1 - bu) + d,         &g_Qhi[(size_t)(b * SEQ + (qt + 1) * 128 + r) * KD + c8]);
                cp16(smb + SCS_Q(1 - bu) + 18432 + d, &g_Qlo[(size_t)(b * SEQ + (qt + 1) * 128 + r) * KD + c8]);
            }
            CP_COMMIT;
        }

        float acc[2][8][4];
        #pragma unroll
        for (int mt = 0; mt < 2; mt++)
            #pragma unroll
            for (int nt = 0; nt < 8; nt++)
                #pragma unroll
                for (int e = 0; e < 4; e++) acc[mt][nt][e] = 0.f;

        const uint32_t kh = smb + SCS_K, kl = kh + 18432;
        const uint32_t qh = smb + SCS_Q(bu), ql = qh + 18432;
        #pragma unroll
        for (int ks = 0; ks < 4; ks++) {
            uint32_t bh[8][2], bl[8][2];
            #pragma unroll
            for (int np = 0; np < 4; np++) {
                uint32_t off = (uint32_t)((jw + np * 16 + arow) * 72 + ks * 16) * 2 + acolB;
                uint32_t r0, r1, r2, r3;
                ldmx4(r0, r1, r2, r3, kh + off);
                bh[np*2][0] = r0; bh[np*2+1][0] = r1; bh[np*2][1] = r2; bh[np*2+1][1] = r3;
                ldmx4(r0, r1, r2, r3, kl + off);
                bl[np*2][0] = r0; bl[np*2+1][0] = r1; bl[np*2][1] = r2; bl[np*2+1][1] = r3;
            }
            #pragma unroll
            for (int mt = 0; mt < 2; mt++) {
                uint32_t off = (uint32_t)((qw + mt * 16 + arow) * 72 + ks * 16) * 2 + acolB;
                uint32_t ah[4], al[4];
                ldmx4(ah[0], ah[1], ah[2], ah[3], qh + off);
                ldmx4(al[0], al[1], al[2], al[3], ql + off);
                #pragma unroll
                for (int nt = 0; nt < 8; nt++) {
                    mma16816(acc[mt][nt], ah, bh[nt]);
                    mma16816(acc[mt][nt], ah, bl[nt]);
                    mma16816(acc[mt][nt], al, bh[nt]);
                }
            }
        }
        CP_WAIT0;

        // mask in place (diag tile only)
        if (qt == jt) {
            #pragma unroll
            for (int mt = 0; mt < 2; mt++)
                #pragma unroll
                for (int nt = 0; nt < 8; nt++) {
                    int jl = jw + nt * 8 + c2;
                    #pragma unroll
                    for (int half = 0; half < 2; half++) {
                        int ql_ = qw + mt * 16 + r4 + half * 8;
                        if (ql_ < jl)     acc[mt][nt][half * 2]     = -1e30f;
                        if (ql_ < jl + 1) acc[mt][nt][half * 2 + 1] = -1e30f;
                    }
                }
        }
        // direct store S [b][q][j] (float2 per fragment pair; sector-aligned)
        {
            const int q0 = qt * 128;
            #pragma unroll
            for (int mt = 0; mt < 2; mt++)
                #pragma unroll
                for (int half = 0; half < 2; half++) {
                    size_t rowb = ((size_t)(b * SEQ + q0 + qw + mt * 16 + r4 + half * 8)) * SEQ + j0 + jw + c2;
                    #pragma unroll
                    for (int nt = 0; nt < 8; nt++)
                        *(float2*)&g_S[rowb + nt * 8] =
                            make_float2(acc[mt][nt][half * 2], acc[mt][nt][half * 2 + 1]);
                }
        }
        // column stats: butterfly over r4 lanes (same j set per cg group)
        {
            float vmax[16];
            #pragma unroll
            for (int s = 0; s < 16; s++) vmax[s] = -1e30f;
            #pragma unroll
            for (int mt = 0; mt < 2; mt++)
                #pragma unroll
                for (int nt = 0; nt < 8; nt++)
                    #pragma unroll
                    for (int half = 0; half < 2; half++) {
                        vmax[nt * 2]     = fmaxf(vmax[nt * 2],     acc[mt][nt][half * 2]);
                        vmax[nt * 2 + 1] = fmaxf(vmax[nt * 2 + 1], acc[mt][nt][half * 2 + 1]);
                    }
            #pragma unroll
            for (int d = 4; d <= 16; d <<= 1)
                #pragma unroll
                for (int s = 0; s < 16; s++)
                    vmax[s] = fmaxf(vmax[s], __shfl_xor_sync(0xffffffffu, vmax[s], d));
            float part[16];
            #pragma unroll
            for (int s = 0; s < 16; s++) part[s] = 0.f;
            #pragma unroll
            for (int mt = 0; mt < 2; mt++)
                #pragma unroll
                for (int nt = 0; nt < 8; nt++)
                    #pragma unroll
                    for (int half = 0; half < 2; half++) {
                        float v0 = acc[mt][nt][half * 2], v1 = acc[mt][nt][half * 2 + 1];
                        part[nt * 2]     += (v0 > -1e29f) ? __expf(v0 - vmax[nt * 2])     : 0.f;
                        part[nt * 2 + 1] += (v1 > -1e29f) ? __expf(v1 - vmax[nt * 2 + 1]) : 0.f;
                    }
            #pragma unroll
            for (int d = 4; d <= 16; d <<= 1)
                #pragma unroll
                for (int s = 0; s < 16; s++)
                    part[s] += __shfl_xor_sync(0xffffffffu, part[s], d);
            #pragma unroll
            for (int e = 0; e < 2; e++) {
                float mb = vmax[2 * r4 + e], lb = part[2 * r4 + e];
                float M = fmaxf(mrun[e], mb);
                float L = ((mrun[e] > -1e29f) ? lrun[e] * __expf(mrun[e] - M) : 0.f)
                        + ((mb > -1e29f) ? lb * __expf(mb - M) : 0.f);
                mrun[e] = M; lrun[e] = L;
            }
        }
    }
    __syncthreads();   // all MMA/Q reads done; safe to reuse Q(0) region
    // per-warp stats -> smem: stat[qw warp][128 j]
    float2* stat = (float2*)(smc + SCS_Q(0));
    {
        int qwid = w & 3;
        int jloc = jw + r4 * 8 + c2;      // this lane owns j = jloc, jloc+1
        stat[qwid * 128 + jloc]     = make_float2(mrun[0], lrun[0]);
        stat[qwid * 128 + jloc + 1] = make_float2(mrun[1], lrun[1]);
    }
    __syncthreads();
    if (tid < 128) {
        float M = -1e30f;
        #pragma unroll
        for (int c = 0; c < 4; c++) M = fmaxf(M, stat[c * 128 + tid].x);
        float L = 0.f;
        #pragma unroll
        for (int c = 0; c < 4; c++) {
            float2 p = stat[c * 128 + tid];
            L += (p.x > -1e29f) ? p.y * __expf(p.x - M) : 0.f;
        }
        g_ml[chunk][b][j0 + tid] = make_float2(M, L);
    }
}

// =========================== k_combine ===========================
__global__ void k_combine()
{
    int idx = blockIdx.x * 256 + threadIdx.x;
    if (idx >= BB * SEQ) return;
    int b = idx >> 12, j = idx & (SEQ - 1);
    int jt = j >> 7;
    int nc = (NQT - 1 - jt) / SC_QCHUNK + 1;
    float M = -1e30f;
    for (int c = 0; c < nc; c++) M = fmaxf(M, g_ml[c][b][j].x);
    float L = 0.f;
    for (int c = 0; c < nc; c++) {
        float2 p = g_ml[c][b][j];
        L += (p.x > -1e29f) ? p.y * __expf(p.x - M) : 0.f;
    }
    g_c[b][j] = M + logf(L);
}

// =========================== k_out (64-wide j chunks, 2 CTAs/SM — R16 winner, unchanged) ===========================
#define KOS_P 0
#define KOS_V(bu) (36864 + (bu) * 36864)
#define SM_KO 110592

__device__ __forceinline__ void ko_cpV(uint32_t smb, int b, int jc, int bu, int tid) {
    for (int i = tid; i < 128 * 8; i += 256) {
        int r = i >> 3, c8 = (i & 7) * 8;
        uint32_t d = (uint32_t)(r * 72 + c8) * 2;
        cp16(smb + KOS_V(bu) + d,         &g_Vthi[((size_t)(b * VD + r)) * SEQ + jc * 64 + c8]);
        cp16(smb + KOS_V(bu) + 18432 + d, &g_Vtlo[((size_t)(b * VD + r)) * SEQ + jc * 64 + c8]);
    }
    CP_COMMIT;
}
__device__ __forceinline__ void ko_fillP(char* smc, int b, int q0, int jc, int tid) {
    const int rr = tid >> 1, hf = tid & 1;
    __nv_bfloat16* Ph = (__nv_bfloat16*)(smc + KOS_P);
    __nv_bfloat16* Pl = (__nv_bfloat16*)(smc + KOS_P + 18432);
    const float* srow = &g_S[((size_t)(b * SEQ + q0 + rr)) * SEQ + jc * 64 + hf * 32];
    const float* crow = &g_c[b][jc * 64 + hf * 32];
    #pragma unroll
    for (int i = 0; i < 4; i++) {
        float4 sa = ((const float4*)srow)[i * 2];
        float4 sb = ((const float4*)srow)[i * 2 + 1];
        uint32_t hw[4], lw[4];
        split_pack(__expf(sa.x - crow[i*8+0]), __expf(sa.y - crow[i*8+1]), hw[0], lw[0]);
        split_pack(__expf(sa.z - crow[i*8+2]), __expf(sa.w - crow[i*8+3]), hw[1], lw[1]);
        split_pack(__expf(sb.x - crow[i*8+4]), __expf(sb.y - crow[i*8+5]), hw[2], lw[2]);
        split_pack(__expf(sb.z - crow[i*8+6]), __expf(sb.w - crow[i*8+7]), hw[3], lw[3]);
        *(uint4*)&Ph[rr * 72 + hf * 32 + i * 8] = make_uint4(hw[0], hw[1], hw[2], hw[3]);
        *(uint4*)&Pl[rr * 72 + hf * 32 + i * 8] = make_uint4(lw[0], lw[1], lw[2], lw[3]);
    }
}

__global__ __launch_bounds__(256, 2) void k_out()
{
    extern __shared__ char smc[];
    const uint32_t smb = smem_u32(smc);
    const int tid = threadIdx.x, lane = tid & 31, w = tid >> 5;
    const int r4 = lane >> 2, c2 = (lane & 3) * 2;
    const int qw = (w & 3) * 32, vw = (w >> 2) * 64;
    const int idx8 = lane & 7, grp = lane >> 3;
    const int arow = (grp & 1) * 8 + idx8;
    const int acolB = (grp >> 1) * 16;
    const int qt = blockIdx.x, chunk = blockIdx.y, b = blockIdx.z;
    int jt0 = chunk * OUT_JCHUNK;
    if (jt0 > qt) return;
    int jt1 = min(jt0 + OUT_JCHUNK - 1, qt);
    const int q0 = qt * 128;
    const int jc0 = jt0 * 2, nch = (jt1 - jt0 + 1) * 2;

    float acc[2][8][4];
    #pragma unroll
    for (int mt = 0; mt < 2; mt++)
        #pragma unroll
        for (int nt = 0; nt < 8; nt++)
            #pragma unroll
            for (int e = 0; e < 4; e++) acc[mt][nt][e] = 0.f;

    ko_cpV(smb, b, jc0, 0, tid);
    ko_fillP(smc, b, q0, jc0, tid);
    CP_WAIT0;
    __syncthreads();

    for (int c = 0; c < nch; c++) {
        const int bu = c & 1;
        if (c + 1 < nch) ko_cpV(smb, b, jc0 + c + 1, 1 - bu, tid);

        const uint32_t ph = smb + KOS_P, pl = ph + 18432;
        const uint32_t vh = smb + KOS_V(bu), vl = vh + 18432;
        #pragma unroll
        for (int ks = 0; ks < 4; ks++) {
            uint32_t ah[2][4], al[2][4];
            #pragma unroll
            for (int mt = 0; mt < 2; mt++) {
                uint32_t offA = (uint32_t)((qw + mt * 16 + arow) * 72 + ks * 16) * 2 + acolB;
                ldmx4(ah[mt][0], ah[mt][1], ah[mt][2], ah[mt][3], ph + offA);
                ldmx4(al[mt][0], al[mt][1], al[mt][2], al[mt][3], pl + offA);
            }
            #pragma unroll
            for (int np = 0; np < 4; np++) {
                uint32_t offB = (uint32_t)((vw + np * 16 + arow) * 72 + ks * 16) * 2 + acolB;
                uint32_t x0, x1, x2, x3, y0, y1, y2, y3;
                ldmx4(x0, x1, x2, x3, vh + offB);
                ldmx4(y0, y1, y2, y3, vl + offB);
                uint32_t bhA[2] = {x0, x2}, bhB[2] = {x1, x3};
                uint32_t blA[2] = {y0, y2}, blB[2] = {y1, y3};
                #pragma unroll
                for (int mt = 0; mt < 2; mt++) {
                    mma16816(acc[mt][2*np],     ah[mt], bhA);
                    mma16816(acc[mt][2*np],     ah[mt], blA);
                    mma16816(acc[mt][2*np],     al[mt], bhA);
                    mma16816(acc[mt][2*np + 1], ah[mt], bhB);
                    mma16816(acc[mt][2*np + 1], ah[mt], blB);
                    mma16816(acc[mt][2*np + 1], al[mt], bhB);
                }
            }
        }
        __syncthreads();                      // P reads done
        if (c + 1 < nch) {
            ko_fillP(smc, b, q0, jc0 + c + 1, tid);
            CP_WAIT0;
        }
        __syncthreads();
    }
    // deterministic partials
    #pragma unroll
    for (int mt = 0; mt < 2; mt++)
        #pragma unroll
        for (int nt = 0; nt < 8; nt++) {
            int vl_ = vw + nt * 8 + c2;
            #pragma unroll
            for (int half = 0; half < 2; half++) {
                int ql_ = qw + mt * 16 + r4 + half * 8;
                *(float2*)&g_Opart[chunk][b][q0 + ql_][vl_] =
                    make_float2(acc[mt][nt][half * 2], acc[mt][nt][half * 2 + 1]);
            }
        }
}

// =========================== k_reduce (sum partials + concat x) ===========================
__global__ void k_reduce(const float* __restrict__ x, float* __restrict__ out)
{
    int idx = blockIdx.x * 256 + threadIdx.x;
    if (idx >= BB * SEQ * 64) return;
    int c4 = (idx & 63) * 4;
    int row = idx >> 6;
    int s = row & (SEQ - 1);
    int b = row >> 12;
    float4 v;
    if (c4 < 128) {
        v = *(const float4*)&x[(size_t)row * 128 + c4];
    } else {
        int vc = c4 - 128;
        int nc = (s >> 7) / OUT_JCHUNK + 1;
        v = make_float4(0.f, 0.f, 0.f, 0.f);
        for (int c = 0; c < nc; c++) {
            float4 p = *(const float4*)&g_Opart[c][b][s][vc];
            v.x += p.x; v.y += p.y; v.z += p.z; v.w += p.w;
        }
    }
    *(float4*)&out[(size_t)row * 256 + c4] = v;
}

// =========================== launch ===========================
extern "C" void kernel_launch(void* const* d_in, const int* in_sizes, int n_in,
                              void* d_out, int out_size)
{
    const float* x  = (const float*)d_in[0];
    const float* Wq = (const float*)d_in[1];
    const float* bq = (const float*)d_in[2];
    const float* Wk = (const float*)d_in[3];
    const float* bk = (const float*)d_in[4];
    const float* Wv = (const float*)d_in[5];
    const float* bv = (const float*)d_in[6];
    float* out = (float*)d_out;

    const int SM_PROJ = (128 * 133 * 2) * 4;

    cudaFuncSetAttribute(k_proj,   cudaFuncAttributeMaxDynamicSharedMemorySize, SM_PROJ);
    cudaFuncSetAttribute(k_scores, cudaFuncAttributeMaxDynamicSharedMemorySize, SM_SC);
    cudaFuncSetAttribute(k_out,    cudaFuncAttributeMaxDynamicSharedMemorySize, SM_KO);

    k_proj<<<dim3(128, 2), 256, SM_PROJ>>>(x, Wq, bq, Wk, bk, Wv, bv);
    k_scores<<<dim3(NJT, N_SCHUNK, BB), 256, SM_SC>>>();
    k_combine<<<(BB * SEQ + 255) / 256, 256>>>();
    k_out<<<dim3(NQT, N_OCHUNK, BB), 256, SM_KO>>>();
    k_reduce<<<(BB * SEQ * 64 + 255) / 256, 256>>>(x, out);
}